// round 3
// baseline (speedup 1.0000x reference)
#include <cuda_runtime.h>

// LSTM T=512, B=4096, I=10, H=20. One WARP per batch row, zero block barriers.
// 80 gate-rows padded to 96 (=4 gates x 24 units); each lane owns 3 gate-rows
// (weights in registers as f32x2), computes + activates them, routes activated
// gates via warp-private smem (__syncwarp only). Lanes 0-19 do the c/h update.
// fma.rn.f32x2 packed math; tanh.approx MUFU for all activations.

#define T_STEPS 512
#define BATCH   4096
#define ISZ     10
#define HSZ     20
#define JPAD    24                 // padded hidden
#define WARPS_PER_CTA 4
#define NTHREADS (WARPS_PER_CTA * 32)

typedef unsigned long long u64;

__device__ __forceinline__ u64 pack2(float x, float y) {
    u64 r; asm("mov.b64 %0, {%1,%2};" : "=l"(r) : "f"(x), "f"(y)); return r;
}
__device__ __forceinline__ void unpack2(u64 v, float& x, float& y) {
    asm("mov.b64 {%0,%1}, %2;" : "=f"(x), "=f"(y) : "l"(v));
}
__device__ __forceinline__ u64 ffma2(u64 a, u64 b, u64 c) {
    u64 r; asm("fma.rn.f32x2 %0, %1, %2, %3;" : "=l"(r) : "l"(a), "l"(b), "l"(c));
    return r;
}
__device__ __forceinline__ float tanh_fast(float x) {
    float y; asm("tanh.approx.f32 %0, %1;" : "=f"(y) : "f"(x)); return y;
}

// per-warp smem region: h double buffer (2x24) + activated gate buffer (96)
#define WREG_F (2 * JPAD + 4 * JPAD)   // 144 floats

__global__ void __launch_bounds__(NTHREADS, 4) lstm_warp_kernel(
    const float* __restrict__ x,      // [T, B, I]
    const float* __restrict__ h0,     // [B, H]
    const float* __restrict__ c0,     // [B, H]
    const float* __restrict__ Wih,    // [4H, I]
    const float* __restrict__ Whh,    // [4H, H]
    const float* __restrict__ bih,    // [4H]
    const float* __restrict__ bhh,    // [4H]
    float* __restrict__ out,
    long long out_size)
{
    const int lane = threadIdx.x & 31;
    const int w    = threadIdx.x >> 5;
    const int b    = blockIdx.x * WARPS_PER_CTA + w;   // batch row for this warp

    __shared__ __align__(16) float sm[WARPS_PER_CTA][WREG_F];
    float* const hbuf = &sm[w][0];          // [2][JPAD]
    float* const gbuf = &sm[w][2 * JPAD];   // [96] activated gates, g*24+j

    // ---- per-lane weights: 3 padded gate-rows r = 3*lane + rr ----
    u64 wih2[3][ISZ / 2];
    u64 whh2[3][HSZ / 2];
    u64 bias2[3];
    float s_[3], o_[3];
#pragma unroll
    for (int rr = 0; rr < 3; rr++) {
        const int r  = 3 * lane + rr;       // 0..95
        const int g  = r / JPAD;            // gate 0..3 (i,f,g,o)
        const int jj = r - g * JPAD;        // padded unit
        const bool valid = (jj < HSZ);
        const int row = g * HSZ + jj;       // row in real weight matrices
        if (valid) {
            const float* wr = Wih + row * ISZ;
#pragma unroll
            for (int k = 0; k < ISZ / 2; k++)
                wih2[rr][k] = *reinterpret_cast<const u64*>(wr + 2 * k);
            const float* wr2 = Whh + row * HSZ;
#pragma unroll
            for (int k = 0; k < HSZ / 2; k++)
                whh2[rr][k] = *reinterpret_cast<const u64*>(wr2 + 2 * k);
            bias2[rr] = pack2(bih[row] + bhh[row], 0.0f);
        } else {
#pragma unroll
            for (int k = 0; k < ISZ / 2; k++) wih2[rr][k] = 0ull;
#pragma unroll
            for (int k = 0; k < HSZ / 2; k++) whh2[rr][k] = 0ull;
            bias2[rr] = 0ull;
        }
        // unified activation: act(x) = fma(tanh(s*x), s, 1-s)
        //   gate 2 (g): s=1   -> tanh
        //   others    : s=0.5 -> sigmoid
        s_[rr] = (g == 2) ? 1.0f : 0.5f;
        o_[rr] = 1.0f - s_[rr];
    }

    // ---- init state ----
    float c = 0.0f, hn = 0.0f;
    if (lane < HSZ) {
        c = c0[(size_t)b * HSZ + lane];
        hbuf[lane] = h0[(size_t)b * HSZ + lane];
    }
    __syncwarp();

    const float* xp = x + (size_t)b * ISZ;          // += B*I per step
    float*       op = out + (size_t)b * HSZ;        // += B*H per step
    const size_t x_step = (size_t)BATCH * ISZ;
    const size_t o_step = (size_t)BATCH * HSZ;

    for (int t = 0; t < T_STEPS; t++) {
        float* const hcur = hbuf + (t & 1) * JPAD;
        float* const hnxt = hbuf + ((t & 1) ^ 1) * JPAD;

        // ---- phase 1: all 32 lanes accumulate + activate their 3 gate-rows
        u64 a0 = bias2[0], a1 = bias2[1], a2 = bias2[2];

        // x projection (lane-broadcast loads, 40B row)
#pragma unroll
        for (int k = 0; k < ISZ / 2; k++) {
            const u64 xv = *reinterpret_cast<const u64*>(xp + 2 * k);
            a0 = ffma2(wih2[0][k], xv, a0);
            a1 = ffma2(wih2[1][k], xv, a1);
            a2 = ffma2(wih2[2][k], xv, a2);
        }

        // recurrent projection: h in 16B chunks (broadcast LDS.128)
#pragma unroll
        for (int k4 = 0; k4 < HSZ / 4; k4++) {
            const ulonglong2 hv = *reinterpret_cast<const ulonglong2*>(hcur + 4 * k4);
            a0 = ffma2(whh2[0][2 * k4], hv.x, a0);
            a1 = ffma2(whh2[1][2 * k4], hv.x, a1);
            a2 = ffma2(whh2[2][2 * k4], hv.x, a2);
            a0 = ffma2(whh2[0][2 * k4 + 1], hv.y, a0);
            a1 = ffma2(whh2[1][2 * k4 + 1], hv.y, a1);
            a2 = ffma2(whh2[2][2 * k4 + 1], hv.y, a2);
        }

        float lo, hi;
        unpack2(a0, lo, hi);
        const float v0 = fmaf(tanh_fast(s_[0] * (lo + hi)), s_[0], o_[0]);
        unpack2(a1, lo, hi);
        const float v1 = fmaf(tanh_fast(s_[1] * (lo + hi)), s_[1], o_[1]);
        unpack2(a2, lo, hi);
        const float v2 = fmaf(tanh_fast(s_[2] * (lo + hi)), s_[2], o_[2]);

        gbuf[3 * lane + 0] = v0;     // stride-3: conflict-free (gcd(3,32)=1)
        gbuf[3 * lane + 1] = v1;
        gbuf[3 * lane + 2] = v2;
        __syncwarp();

        // ---- phase 2: lanes 0..19 update c, h for unit j = lane
        if (lane < HSZ) {
            const float gi = gbuf[lane];
            const float gf = gbuf[JPAD + lane];
            const float gg = gbuf[2 * JPAD + lane];
            const float go = gbuf[3 * JPAD + lane];
            c  = fmaf(gf, c, gi * gg);
            hn = go * tanh_fast(c);
            hnxt[lane] = hn;
            op[lane]   = hn;
        }
        __syncwarp();

        xp += x_step;
        op += o_step;
    }

    // ---- final h, c appended after outputs ----
    const long long base = (long long)T_STEPS * BATCH * HSZ;
    if (lane < HSZ && out_size >= base + 2LL * BATCH * HSZ) {
        out[base + (size_t)b * HSZ + lane] = hn;
        out[base + (size_t)BATCH * HSZ + (size_t)b * HSZ + lane] = c;
    }
}

extern "C" void kernel_launch(void* const* d_in, const int* in_sizes, int n_in,
                              void* d_out, int out_size) {
    const float* x   = (const float*)d_in[0];
    const float* h0  = (const float*)d_in[1];
    const float* c0  = (const float*)d_in[2];
    const float* Wih = (const float*)d_in[3];
    const float* Whh = (const float*)d_in[4];
    const float* bih = (const float*)d_in[5];
    const float* bhh = (const float*)d_in[6];
    float* out = (float*)d_out;

    dim3 grid(BATCH / WARPS_PER_CTA);   // 1024 CTAs, one warp per batch row
    dim3 block(NTHREADS);               // 128 threads
    lstm_warp_kernel<<<grid, block>>>(x, h0, c0, Wih, Whh, bih, bhh,
                                      out, (long long)out_size);
}